// round 1
// baseline (speedup 1.0000x reference)
#include <cuda_runtime.h>
#include <cstdint>

#define NSAMP 128
#define RAYS_PER_BLOCK 8
#define THREADS (RAYS_PER_BLOCK * 32)
#define MAX_RAYS 8192

// Scratch: per-ray partial sums (allocation-free per harness rules)
__device__ float g_partials[MAX_RAYS];

__device__ __forceinline__ uint64_t pack_f32x2(float lo, float hi) {
    uint64_t r;
    asm("mov.b64 %0, {%1, %2};" : "=l"(r) : "f"(lo), "f"(hi));
    return r;
}
__device__ __forceinline__ void unpack_f32x2(uint64_t v, float& lo, float& hi) {
    asm("mov.b64 {%0, %1}, %2;" : "=f"(lo), "=f"(hi) : "l"(v));
}
__device__ __forceinline__ uint64_t add_f32x2(uint64_t a, uint64_t b) {
    uint64_t r;
    asm("add.rn.f32x2 %0, %1, %2;" : "=l"(r) : "l"(a), "l"(b));
    return r;
}
__device__ __forceinline__ uint64_t fma_f32x2(uint64_t a, uint64_t b, uint64_t c) {
    uint64_t r;
    asm("fma.rn.f32x2 %0, %1, %2, %3;" : "=l"(r) : "l"(a), "l"(b), "l"(c));
    return r;
}

// One warp per ray. Each lane owns 4 consecutive i-samples as 2 packed f32x2
// accumulators. SMEM holds per-ray {(-m,-m),(w,w)} so the j-loop body is:
//   LDS.128 (broadcast) ; 2x add.f32x2 ; 4x LOP3 (abs) ; 2x fma.f32x2
// FMA pipe and ALU pipe each get 4 ops/iter -> balanced.
__global__ void __launch_bounds__(THREADS)
interval_loss_main(const float* __restrict__ z_vals,
                   const float* __restrict__ deltas,
                   const float* __restrict__ weights,
                   int nrays)
{
    __shared__ ulonglong2 tile[RAYS_PER_BLOCK][NSAMP];

    const int warp = threadIdx.x >> 5;
    const int lane = threadIdx.x & 31;
    const int ray  = blockIdx.x * RAYS_PER_BLOCK + warp;
    if (ray >= nrays) return;  // whole-warp uniform

    const size_t base = (size_t)ray * NSAMP;
    const float* zr = z_vals  + base;
    const float* dr = deltas  + base;
    const float* wr = weights + base;

    // Load phase: coalesced strided loads; also accumulate term_1 = sum w^2 * d
    float t1 = 0.0f;
#pragma unroll
    for (int k = 0; k < 4; k++) {
        int idx = lane + 32 * k;
        float zz = zr[idx];
        float dd = dr[idx];
        float ww = wr[idx];
        float m  = fmaf(0.5f, dd, zz);
        tile[warp][idx] = make_ulonglong2(pack_f32x2(-m, -m), pack_f32x2(ww, ww));
        t1 = fmaf(ww * ww, dd, t1);
    }
    __syncwarp();

    // Gather this lane's own 4 i-samples (consecutive: 4*lane .. 4*lane+3)
    float mi[4], wi[4];
#pragma unroll
    for (int k = 0; k < 4; k++) {
        ulonglong2 q = tile[warp][4 * lane + k];
        float nm0, nm1, w0, w1;
        unpack_f32x2(q.x, nm0, nm1);
        unpack_f32x2(q.y, w0, w1);
        mi[k] = -nm0;
        wi[k] = w0;
    }
    const uint64_t mi2a = pack_f32x2(mi[0], mi[1]);
    const uint64_t mi2b = pack_f32x2(mi[2], mi[3]);

    const ulonglong2* __restrict__ row = tile[warp];
    uint64_t acc_a = 0ULL;  // packed (0.0f, 0.0f)
    uint64_t acc_b = 0ULL;
    const uint64_t ABSMASK = 0x7FFFFFFF7FFFFFFFULL;

#pragma unroll 16
    for (int j = 0; j < NSAMP; j++) {
        ulonglong2 q = row[j];                       // LDS.128 broadcast
        uint64_t da = add_f32x2(mi2a, q.x) & ABSMASK; // |m_i - m_j| x2
        uint64_t db = add_f32x2(mi2b, q.x) & ABSMASK;
        acc_a = fma_f32x2(q.y, da, acc_a);            // += w_j * |.|
        acc_b = fma_f32x2(q.y, db, acc_b);
    }

    float a0, a1, a2, a3;
    unpack_f32x2(acc_a, a0, a1);
    unpack_f32x2(acc_b, a2, a3);

    // per-lane: sum_i w_i * (sum_j w_j |m_i - m_j|)  (= term_0 contribution)
    float s = wi[0] * a0 + wi[1] * a1 + wi[2] * a2 + wi[3] * a3;
    float val = 0.5f * s + (1.0f / 3.0f) * t1;

    // warp reduction
#pragma unroll
    for (int off = 16; off > 0; off >>= 1)
        val += __shfl_xor_sync(0xFFFFFFFFu, val, off);

    if (lane == 0)
        g_partials[ray] = val;
}

__global__ void __launch_bounds__(256)
interval_loss_reduce(const int* __restrict__ num_pixels,
                     float* __restrict__ out, int nrays)
{
    __shared__ float sh[256];
    float s = 0.0f;
    for (int i = threadIdx.x; i < nrays; i += 256)
        s += g_partials[i];
    sh[threadIdx.x] = s;
    __syncthreads();
#pragma unroll
    for (int off = 128; off > 0; off >>= 1) {
        if (threadIdx.x < off) sh[threadIdx.x] += sh[threadIdx.x + off];
        __syncthreads();
    }
    if (threadIdx.x == 0)
        out[0] = 0.01f * sh[0] / (float)num_pixels[0];
}

extern "C" void kernel_launch(void* const* d_in, const int* in_sizes, int n_in,
                              void* d_out, int out_size)
{
    const float* z_vals  = (const float*)d_in[0];
    const float* deltas  = (const float*)d_in[1];
    const float* weights = (const float*)d_in[2];
    const int*   npix    = (const int*)d_in[3];

    int total = in_sizes[0];
    int nrays = total / NSAMP;
    if (nrays > MAX_RAYS) nrays = MAX_RAYS;

    int blocks = (nrays + RAYS_PER_BLOCK - 1) / RAYS_PER_BLOCK;
    interval_loss_main<<<blocks, THREADS>>>(z_vals, deltas, weights, nrays);
    interval_loss_reduce<<<1, 256>>>(npix, (float*)d_out, nrays);
}

// round 5
// speedup vs baseline: 1.4554x; 1.4554x over previous
#include <cuda_runtime.h>
#include <cstdint>

#define NSAMP 128
#define RPB 8                      // rays (warps) per block
#define THREADS (RPB * 32)
#define MAXB 4096

// Scratch (allocation-free per harness rules)
__device__ float g_block_partials[MAXB];
__device__ unsigned int g_arrival = 0;

static __device__ __forceinline__ unsigned long long pack2(float lo, float hi) {
    unsigned long long r;
    asm("mov.b64 %0, {%1, %2};" : "=l"(r) : "f"(lo), "f"(hi));
    return r;
}
static __device__ __forceinline__ void unpack2(unsigned long long v, float& lo, float& hi) {
    asm("mov.b64 {%0, %1}, %2;" : "=f"(lo), "=f"(hi) : "l"(v));
}
static __device__ __forceinline__ unsigned long long add2(unsigned long long a, unsigned long long b) {
    unsigned long long r;
    asm("add.rn.f32x2 %0, %1, %2;" : "=l"(r) : "l"(a), "l"(b));
    return r;
}
static __device__ __forceinline__ unsigned long long fma2(unsigned long long a, unsigned long long b, unsigned long long c) {
    unsigned long long r;
    asm("fma.rn.f32x2 %0, %1, %2, %3;" : "=l"(r) : "l"(a), "l"(b), "l"(c));
    return r;
}
static __device__ __forceinline__ unsigned long long mul2(unsigned long long a, unsigned long long b) {
    unsigned long long r;
    asm("mul.rn.f32x2 %0, %1, %2;" : "=l"(r) : "l"(a), "l"(b));
    return r;
}

// One warp per ray. Lane L owns samples 4L..4L+3.
// Rotation: step o pairs lane L's block with lane (L+o)&31's block.
//   o = 1..15 : each unordered cross-block pair covered exactly once
//   o = 16    : covered twice (L and L+16) -> w_j pre-scaled by 0.5
//   o = 0     : 6 intra-block pairs, scalar
// Accumulates term_0/2 + term_1/3 directly; single fused kernel with
// last-block final reduction (deterministic fixed-order sums).
__global__ void __launch_bounds__(THREADS)
interval_loss_fused(const float* __restrict__ z_vals,
                    const float* __restrict__ deltas,
                    const float* __restrict__ weights,
                    const int* __restrict__ npix,
                    float* __restrict__ out,
                    int nrays)
{
    const int lane = threadIdx.x & 31;
    const int warp = threadIdx.x >> 5;
    const int ray  = blockIdx.x * RPB + warp;

    float val = 0.0f;

    if (ray < nrays) {                                   // warp-uniform
        const float4* __restrict__ z4 = (const float4*)z_vals;
        const float4* __restrict__ d4 = (const float4*)deltas;
        const float4* __restrict__ w4 = (const float4*)weights;
        const int q = ray * (NSAMP / 4) + lane;
        const float4 zv = z4[q];
        const float4 dv = d4[q];
        const float4 wv = w4[q];

        const float m0 = fmaf(0.5f, dv.x, zv.x);
        const float m1 = fmaf(0.5f, dv.y, zv.y);
        const float m2 = fmaf(0.5f, dv.z, zv.z);
        const float m3 = fmaf(0.5f, dv.w, zv.w);

        // term_1 partial: sum w^2 * delta over own 4 samples
        float t1 = wv.x * wv.x * dv.x;
        t1 = fmaf(wv.y * wv.y, dv.y, t1);
        t1 = fmaf(wv.z * wv.z, dv.z, t1);
        t1 = fmaf(wv.w * wv.w, dv.w, t1);

        // own i-side packed (m0,m1) / (m2,m3)
        const unsigned long long mi_a = pack2(m0, m1);
        const unsigned long long mi_b = pack2(m2, m3);

        // broadcast copies: duplicated (-m,-m) and (w,w) per own sample
        const unsigned long long om0 = pack2(-m0, -m0);
        const unsigned long long om1 = pack2(-m1, -m1);
        const unsigned long long om2v = pack2(-m2, -m2);
        const unsigned long long om3 = pack2(-m3, -m3);
        const unsigned long long ow0 = pack2(wv.x, wv.x);
        const unsigned long long ow1 = pack2(wv.y, wv.y);
        const unsigned long long ow2v = pack2(wv.z, wv.z);
        const unsigned long long ow3 = pack2(wv.w, wv.w);

        const unsigned long long ABSM = 0x7FFFFFFF7FFFFFFFULL;
        const unsigned long long HALF2 = pack2(0.5f, 0.5f);

        unsigned long long acc_a = 0ULL;   // (A_i0, A_i1)
        unsigned long long acc_b = 0ULL;   // (A_i2, A_i3)

#pragma unroll
        for (int o = 1; o <= 16; o++) {
            const int src = (lane + o) & 31;
            unsigned long long pm0 = __shfl_sync(0xFFFFFFFFu, om0, src);
            unsigned long long pm1 = __shfl_sync(0xFFFFFFFFu, om1, src);
            unsigned long long pm2 = __shfl_sync(0xFFFFFFFFu, om2v, src);
            unsigned long long pm3 = __shfl_sync(0xFFFFFFFFu, om3, src);
            unsigned long long pw0 = __shfl_sync(0xFFFFFFFFu, ow0, src);
            unsigned long long pw1 = __shfl_sync(0xFFFFFFFFu, ow1, src);
            unsigned long long pw2 = __shfl_sync(0xFFFFFFFFu, ow2v, src);
            unsigned long long pw3 = __shfl_sync(0xFFFFFFFFu, ow3, src);

            if (o == 16) {   // pair {L, L+16} covered by both lanes -> half weight
                pw0 = mul2(pw0, HALF2);
                pw1 = mul2(pw1, HALF2);
                pw2 = mul2(pw2, HALF2);
                pw3 = mul2(pw3, HALF2);
            }

            unsigned long long da, db;
            da = add2(mi_a, pm0) & ABSM;  db = add2(mi_b, pm0) & ABSM;
            acc_a = fma2(pw0, da, acc_a); acc_b = fma2(pw0, db, acc_b);
            da = add2(mi_a, pm1) & ABSM;  db = add2(mi_b, pm1) & ABSM;
            acc_a = fma2(pw1, da, acc_a); acc_b = fma2(pw1, db, acc_b);
            da = add2(mi_a, pm2) & ABSM;  db = add2(mi_b, pm2) & ABSM;
            acc_a = fma2(pw2, da, acc_a); acc_b = fma2(pw2, db, acc_b);
            da = add2(mi_a, pm3) & ABSM;  db = add2(mi_b, pm3) & ABSM;
            acc_a = fma2(pw3, da, acc_a); acc_b = fma2(pw3, db, acc_b);
        }

        float a0, a1, a2, a3;
        unpack2(acc_a, a0, a1);
        unpack2(acc_b, a2, a3);

        // cross-block contribution: sum_i w_i * A_i
        float s = wv.x * a0;
        s = fmaf(wv.y, a1, s);
        s = fmaf(wv.z, a2, s);
        s = fmaf(wv.w, a3, s);

        // intra-block (o=0): 6 unordered pairs
        s = fmaf(wv.x * wv.y, fabsf(m0 - m1), s);
        s = fmaf(wv.x * wv.z, fabsf(m0 - m2), s);
        s = fmaf(wv.x * wv.w, fabsf(m0 - m3), s);
        s = fmaf(wv.y * wv.z, fabsf(m1 - m2), s);
        s = fmaf(wv.y * wv.w, fabsf(m1 - m3), s);
        s = fmaf(wv.z * wv.w, fabsf(m2 - m3), s);

        val = s + t1 * (1.0f / 3.0f);   // term_0/2 + term_1/3 share
    }

    // warp reduction
#pragma unroll
    for (int off = 16; off > 0; off >>= 1)
        val += __shfl_xor_sync(0xFFFFFFFFu, val, off);

    __shared__ float sh[RPB];
    if (lane == 0) sh[warp] = val;
    __syncthreads();

    if (warp == 0) {
        float b = (lane < RPB) ? sh[lane] : 0.0f;
        b += __shfl_xor_sync(0xFFFFFFFFu, b, 4);
        b += __shfl_xor_sync(0xFFFFFFFFu, b, 2);
        b += __shfl_xor_sync(0xFFFFFFFFu, b, 1);
        if (lane == 0) g_block_partials[blockIdx.x] = b;
    }

    // last-arriving block performs the final (fixed-order, deterministic) sum
    __shared__ unsigned int sticket;
    if (threadIdx.x == 0) {
        __threadfence();
        sticket = atomicAdd(&g_arrival, 1u);
    }
    __syncthreads();

    if (sticket == gridDim.x - 1) {
        __threadfence();
        float s = 0.0f;
        for (int i = threadIdx.x; i < (int)gridDim.x; i += THREADS)
            s += g_block_partials[i];
#pragma unroll
        for (int off = 16; off > 0; off >>= 1)
            s += __shfl_xor_sync(0xFFFFFFFFu, s, off);
        __shared__ float red[RPB];
        if (lane == 0) red[warp] = s;
        __syncthreads();
        if (threadIdx.x == 0) {
            float tot = 0.0f;
#pragma unroll
            for (int k = 0; k < RPB; k++) tot += red[k];
            out[0] = 0.01f * tot / (float)npix[0];
            g_arrival = 0;   // reset for next graph replay
        }
    }
}

extern "C" void kernel_launch(void* const* d_in, const int* in_sizes, int n_in,
                              void* d_out, int out_size)
{
    const float* z_vals  = (const float*)d_in[0];
    const float* deltas  = (const float*)d_in[1];
    const float* weights = (const float*)d_in[2];
    const int*   npix    = (const int*)d_in[3];

    int total = in_sizes[0];
    int nrays = total / NSAMP;

    int blocks = (nrays + RPB - 1) / RPB;
    if (blocks > MAXB) blocks = MAXB;

    interval_loss_fused<<<blocks, THREADS>>>(z_vals, deltas, weights, npix,
                                             (float*)d_out, nrays);
}

// round 6
// speedup vs baseline: 1.6875x; 1.1595x over previous
#include <cuda_runtime.h>
#include <cstdint>

#define NSAMP 128
#define RPB 8                      // rays (warps) per block
#define THREADS (RPB * 32)
#define MAXB 4096

// Scratch (allocation-free per harness rules)
__device__ float g_block_partials[MAXB];
__device__ unsigned int g_arrival = 0;

static __device__ __forceinline__ unsigned long long pack2(float lo, float hi) {
    unsigned long long r;
    asm("mov.b64 %0, {%1, %2};" : "=l"(r) : "f"(lo), "f"(hi));
    return r;
}
static __device__ __forceinline__ void unpack2(unsigned long long v, float& lo, float& hi) {
    asm("mov.b64 {%0, %1}, %2;" : "=f"(lo), "=f"(hi) : "l"(v));
}
static __device__ __forceinline__ unsigned long long add2(unsigned long long a, unsigned long long b) {
    unsigned long long r;
    asm("add.rn.f32x2 %0, %1, %2;" : "=l"(r) : "l"(a), "l"(b));
    return r;
}
static __device__ __forceinline__ unsigned long long fma2(unsigned long long a, unsigned long long b, unsigned long long c) {
    unsigned long long r;
    asm("fma.rn.f32x2 %0, %1, %2, %3;" : "=l"(r) : "l"(a), "l"(b), "l"(c));
    return r;
}
static __device__ __forceinline__ unsigned long long mul2(unsigned long long a, unsigned long long b) {
    unsigned long long r;
    asm("mul.rn.f32x2 %0, %1, %2;" : "=l"(r) : "l"(a), "l"(b));
    return r;
}

// One warp per ray. Lane L owns samples 4L..4L+3.
// Rotation via SMEM: step o pairs lane L's block with block (L+o)&31, read as
// two rotated LDS.128 (packed m-quad and w-quad). i-side is duplicated in
// registers. Step body: 2 LDS.128 + 8 add2 + 8 fma2 + 16 LOP3 = 34 issue slots
// (vs 48 with the shuffle scheme).
//   o = 1..15 : each unordered cross-block pair covered exactly once
//   o = 16    : covered twice (L and L+16) -> w_j pre-scaled by 0.5
//   o = 0     : 6 intra-block pairs, scalar
__global__ void __launch_bounds__(THREADS)
interval_loss_fused(const float* __restrict__ z_vals,
                    const float* __restrict__ deltas,
                    const float* __restrict__ weights,
                    const int* __restrict__ npix,
                    float* __restrict__ out,
                    int nrays)
{
    __shared__ ulonglong2 sm_m[RPB][32];   // per-ray packed mid quads
    __shared__ ulonglong2 sm_w[RPB][32];   // per-ray packed weight quads

    const int lane = threadIdx.x & 31;
    const int warp = threadIdx.x >> 5;
    const int ray  = blockIdx.x * RPB + warp;

    float val = 0.0f;

    if (ray < nrays) {                                   // warp-uniform
        const float4* __restrict__ z4 = (const float4*)z_vals;
        const float4* __restrict__ d4 = (const float4*)deltas;
        const float4* __restrict__ w4 = (const float4*)weights;
        const int q = ray * (NSAMP / 4) + lane;
        const float4 zv = z4[q];
        const float4 dv = d4[q];
        const float4 wv = w4[q];

        const float m0 = fmaf(0.5f, dv.x, zv.x);
        const float m1 = fmaf(0.5f, dv.y, zv.y);
        const float m2 = fmaf(0.5f, dv.z, zv.z);
        const float m3 = fmaf(0.5f, dv.w, zv.w);

        // term_1 partial: sum w^2 * delta over own 4 samples
        float t1 = wv.x * wv.x * dv.x;
        t1 = fmaf(wv.y * wv.y, dv.y, t1);
        t1 = fmaf(wv.z * wv.z, dv.z, t1);
        t1 = fmaf(wv.w * wv.w, dv.w, t1);

        // publish own packed quads to this warp's SMEM row
        sm_m[warp][lane] = make_ulonglong2(pack2(m0, m1), pack2(m2, m3));
        sm_w[warp][lane] = make_ulonglong2(pack2(wv.x, wv.y), pack2(wv.z, wv.w));
        __syncwarp();

        // i-side duplicated negated mids (register constants)
        unsigned long long nmi[4];
        nmi[0] = pack2(-m0, -m0);
        nmi[1] = pack2(-m1, -m1);
        nmi[2] = pack2(-m2, -m2);
        nmi[3] = pack2(-m3, -m3);

        const unsigned long long ABSM = 0x7FFFFFFF7FFFFFFFULL;
        const unsigned long long HALF2 = pack2(0.5f, 0.5f);

        // acc[k]: packed partial A_k over j (two j-lanes each)
        unsigned long long acc[4] = {0ULL, 0ULL, 0ULL, 0ULL};

        const ulonglong2* __restrict__ rowm = sm_m[warp];
        const ulonglong2* __restrict__ roww = sm_w[warp];

#pragma unroll
        for (int o = 1; o <= 16; o++) {
            const int src = (lane + o) & 31;
            ulonglong2 mj = rowm[src];      // (m_j0,m_j1),(m_j2,m_j3)
            ulonglong2 wj = roww[src];      // (w_j0,w_j1),(w_j2,w_j3)

            unsigned long long wja = wj.x, wjb = wj.y;
            if (o == 16) {                  // pair {L, L+16} double-covered
                wja = mul2(wja, HALF2);
                wjb = mul2(wjb, HALF2);
            }

#pragma unroll
            for (int k = 0; k < 4; k++) {
                unsigned long long da = add2(mj.x, nmi[k]) & ABSM;
                acc[k] = fma2(wja, da, acc[k]);
                unsigned long long db = add2(mj.y, nmi[k]) & ABSM;
                acc[k] = fma2(wjb, db, acc[k]);
            }
        }

        float a0l, a0h, a1l, a1h, a2l, a2h, a3l, a3h;
        unpack2(acc[0], a0l, a0h);
        unpack2(acc[1], a1l, a1h);
        unpack2(acc[2], a2l, a2h);
        unpack2(acc[3], a3l, a3h);

        // cross-block contribution: sum_k w_k * A_k
        float s = wv.x * (a0l + a0h);
        s = fmaf(wv.y, (a1l + a1h), s);
        s = fmaf(wv.z, (a2l + a2h), s);
        s = fmaf(wv.w, (a3l + a3h), s);

        // intra-block (o=0): 6 unordered pairs
        s = fmaf(wv.x * wv.y, fabsf(m0 - m1), s);
        s = fmaf(wv.x * wv.z, fabsf(m0 - m2), s);
        s = fmaf(wv.x * wv.w, fabsf(m0 - m3), s);
        s = fmaf(wv.y * wv.z, fabsf(m1 - m2), s);
        s = fmaf(wv.y * wv.w, fabsf(m1 - m3), s);
        s = fmaf(wv.z * wv.w, fabsf(m2 - m3), s);

        val = s + t1 * (1.0f / 3.0f);   // term_0/2 + term_1/3 share
    }

    // warp reduction
#pragma unroll
    for (int off = 16; off > 0; off >>= 1)
        val += __shfl_xor_sync(0xFFFFFFFFu, val, off);

    __shared__ float sh[RPB];
    if (lane == 0) sh[warp] = val;
    __syncthreads();

    if (warp == 0) {
        float b = (lane < RPB) ? sh[lane] : 0.0f;
        b += __shfl_xor_sync(0xFFFFFFFFu, b, 4);
        b += __shfl_xor_sync(0xFFFFFFFFu, b, 2);
        b += __shfl_xor_sync(0xFFFFFFFFu, b, 1);
        if (lane == 0) g_block_partials[blockIdx.x] = b;
    }

    // last-arriving block performs the final (fixed-order, deterministic) sum
    __shared__ unsigned int sticket;
    if (threadIdx.x == 0) {
        __threadfence();
        sticket = atomicAdd(&g_arrival, 1u);
    }
    __syncthreads();

    if (sticket == gridDim.x - 1) {
        __threadfence();
        float s = 0.0f;
        for (int i = threadIdx.x; i < (int)gridDim.x; i += THREADS)
            s += g_block_partials[i];
#pragma unroll
        for (int off = 16; off > 0; off >>= 1)
            s += __shfl_xor_sync(0xFFFFFFFFu, s, off);
        __shared__ float red[RPB];
        if (lane == 0) red[warp] = s;
        __syncthreads();
        if (threadIdx.x == 0) {
            float tot = 0.0f;
#pragma unroll
            for (int k = 0; k < RPB; k++) tot += red[k];
            out[0] = 0.01f * tot / (float)npix[0];
            g_arrival = 0;   // reset for next graph replay
        }
    }
}

extern "C" void kernel_launch(void* const* d_in, const int* in_sizes, int n_in,
                              void* d_out, int out_size)
{
    const float* z_vals  = (const float*)d_in[0];
    const float* deltas  = (const float*)d_in[1];
    const float* weights = (const float*)d_in[2];
    const int*   npix    = (const int*)d_in[3];

    int total = in_sizes[0];
    int nrays = total / NSAMP;

    int blocks = (nrays + RPB - 1) / RPB;
    if (blocks > MAXB) blocks = MAXB;

    interval_loss_fused<<<blocks, THREADS>>>(z_vals, deltas, weights, npix,
                                             (float*)d_out, nrays);
}